// round 12
// baseline (speedup 1.0000x reference)
#include <cuda_runtime.h>
#include <cuda_bf16.h>

#define M_NODES 10000
#define T_STEPS 40
#define KNN     16
#define FSEM    32
#define EPSV    1e-8f

// Merged (tt,j)-indexed record: 32B aligned, a+b in one 32B sector of one line.
// a = (pref.xyz, 1/(2 sig^2+eps)); b = q_rel.
struct __align__(32) ABRec { float4 a, b; };
__device__ ABRec  g_AB[T_STEPS * M_NODES];   // 12.8 MB, L2-resident
__device__ float4 g_C[M_NODES];              // 160 KB -> L1-resident (p_live.xyz, 0)

struct Quat { float w, x, y, z; };

__device__ __forceinline__ Quat qnormalize(Quat q) {
    float n2 = q.w * q.w + q.x * q.x + q.y * q.y + q.z * q.z;
    float inv = rsqrtf(fmaxf(n2, 1e-24f));   // matches reference clip(norm,1e-12)
    Quat r; r.w = q.w * inv; r.x = q.x * inv; r.y = q.y * inv; r.z = q.z * inv;
    return r;
}

__device__ __forceinline__ Quat qload(float4 v) {
    Quat q; q.w = v.x; q.x = v.y; q.y = v.z; q.z = v.w; return q;
}

__device__ __forceinline__ Quat qmul(Quat a, Quat b) {
    Quat r;
    r.w = a.w * b.w - a.x * b.x - a.y * b.y - a.z * b.z;
    r.x = a.w * b.x + a.x * b.w + a.y * b.z - a.z * b.y;
    r.y = a.w * b.y - a.x * b.z + a.y * b.w + a.z * b.x;
    r.z = a.w * b.z + a.x * b.y - a.y * b.x + a.z * b.w;
    return r;
}

// RAW q2R (no internal normalize): for q ~ 0 yields ~I (reference degenerate path).
__device__ __forceinline__ void q2R(Quat q, float R[3][3]) {
    float w = q.w, x = q.x, y = q.y, z = q.z;
    R[0][0] = 1.f - 2.f * (y * y + z * z);
    R[0][1] = 2.f * (x * y - w * z);
    R[0][2] = 2.f * (x * z + w * y);
    R[1][0] = 2.f * (x * y + w * z);
    R[1][1] = 1.f - 2.f * (x * x + z * z);
    R[1][2] = 2.f * (y * z - w * x);
    R[2][0] = 2.f * (x * z - w * y);
    R[2][1] = 2.f * (y * z + w * x);
    R[2][2] = 1.f - 2.f * (x * x + y * y);
}

__device__ __forceinline__ void mat3mul(const float A[3][3], const float B[3][3], float C[3][3]) {
    #pragma unroll
    for (int i = 0; i < 3; i++)
        #pragma unroll
        for (int j = 0; j < 3; j++)
            C[i][j] = A[i][0] * B[0][j] + A[i][1] * B[1][j] + A[i][2] * B[2][j];
}

__device__ __forceinline__ float3 qrot(Quat q, float3 v) {
    float tx = 2.f * (q.y * v.z - q.z * v.y);
    float ty = 2.f * (q.z * v.x - q.x * v.z);
    float tz = 2.f * (q.x * v.y - q.y * v.x);
    float3 r;
    r.x = v.x + q.w * tx + (q.y * tz - q.z * ty);
    r.y = v.y + q.w * ty + (q.z * tx - q.x * tz);
    r.z = v.z + q.w * tz + (q.x * ty - q.y * tx);
    return r;
}

__device__ __forceinline__ float sigmoidf(float x) {
    return 1.f / (1.f + __expf(-x));
}

__device__ __forceinline__ float qw_sum(float v) {
    v += __shfl_xor_sync(0xffffffffu, v, 4);
    v += __shfl_xor_sync(0xffffffffu, v, 2);
    v += __shfl_xor_sync(0xffffffffu, v, 1);
    return v;
}

// ---- precompute kernel: one thread per (tt, j) ----
__global__ void __launch_bounds__(256)
dyn_scf_pre_kernel(
    const float*  __restrict__ node_xyz,
    const float4* __restrict__ node_quat,
    const float*  __restrict__ node_sigma,
    const int*    __restrict__ t_ptr)
{
    int idx = blockIdx.x * blockDim.x + threadIdx.x;
    if (idx >= T_STEPS * M_NODES) return;
    int j  = idx % M_NODES;
    int tt = idx / M_NODES;
    int t  = __ldg(t_ptr);
    long tMj = (long)t * M_NODES + j;

    Quat qr = qnormalize(qload(__ldg(&node_quat[idx])));
    Quat ql = qnormalize(qload(__ldg(&node_quat[tMj])));
    // q_rel = ql * conj(qr)
    float4 B;
    B.x =  ql.w * qr.w + ql.x * qr.x + ql.y * qr.y + ql.z * qr.z;
    B.y = -ql.w * qr.x + ql.x * qr.w - ql.y * qr.z + ql.z * qr.y;
    B.z = -ql.w * qr.y + ql.x * qr.z + ql.y * qr.w - ql.z * qr.x;
    B.w = -ql.w * qr.z - ql.x * qr.y + ql.y * qr.x + ql.z * qr.w;

    float sig = __ldg(&node_sigma[j]);
    float px = __ldg(&node_xyz[3L * idx]);
    float py = __ldg(&node_xyz[3L * idx + 1]);
    float pz = __ldg(&node_xyz[3L * idx + 2]);

    g_AB[idx].a = make_float4(px, py, pz, 1.f / (2.f * sig * sig + EPSV));
    g_AB[idx].b = B;
    if (tt == t) g_C[j] = make_float4(px, py, pz, 0.f);
}

// Per-gaussian front-end state (computed with both chains interleaved for ILP).
struct GState {
    int   n;
    float w0, w1;
    int   j0, j1;
    Quat  q0, q1;
    float3 m0, m1;
    float4 C0, C1;
    Quat  qag;
};

// ---- main kernel: 8 gaussians per warp (each 8-lane group carries TWO) ----
__global__ void __launch_bounds__(256)
dyn_scf_qw_kernel(
    const float*  __restrict__ gs_xyz,     // (N,3)
    const float4* __restrict__ gs_rot,     // (N,4)
    const float4* __restrict__ node_quat,  // (T,M,4)
    const float4* __restrict__ node_sem4,  // (M,32) as M x 8 float4
    const int*    __restrict__ attach,     // (N,)
    const int*    __restrict__ ref_time,   // (N,)
    const int2*   __restrict__ topo2,      // (M,K) as M x 8 int2
    float*        __restrict__ out,
    int N)
{
    const int lane = threadIdx.x & 31;
    const int kl   = lane & 7;
    const int grp  = (lane >> 3) & 3;
    const long warp_gid = (long)blockIdx.x * (blockDim.x >> 5) + (threadIdx.x >> 5);
    const int base = (int)(warp_gid * 8);
    const int nA = base + grp;
    if (nA >= N) return;        // N % 8 == 0 -> nB valid iff nA valid
    const int nB = base + grp + 4;

    // ---- front-end: both chains fully interleaved (independent -> 2x MLP) ----
    const int aA  = __ldg(&attach[nA]);
    const int aB  = __ldg(&attach[nB]);
    const int rtA = __ldg(&ref_time[nA]);
    const int rtB = __ldg(&ref_time[nB]);
    const long rtMA = (long)rtA * M_NODES;
    const long rtMB = (long)rtB * M_NODES;

    const int2 jjA = __ldg(&topo2[aA * (KNN / 2) + kl]);
    const int2 jjB = __ldg(&topo2[aB * (KNN / 2) + kl]);

    const ABRec* PA0 = &g_AB[rtMA + jjA.x];
    const ABRec* PA1 = &g_AB[rtMA + jjA.y];
    const ABRec* PB0 = &g_AB[rtMB + jjB.x];
    const ABRec* PB1 = &g_AB[rtMB + jjB.y];
    float4 A0a = __ldg(&PA0->a);
    float4 A1a = __ldg(&PA1->a);
    float4 A0b = __ldg(&PB0->a);
    float4 A1b = __ldg(&PB1->a);
    float4 B0a = __ldg(&PA0->b);
    float4 B1a = __ldg(&PA1->b);
    float4 B0b = __ldg(&PB0->b);
    float4 B1b = __ldg(&PB1->b);

    GState A, B;
    A.n = nA; B.n = nB;
    A.j0 = jjA.x; A.j1 = jjA.y;
    B.j0 = jjB.x; B.j1 = jjB.y;
    A.C0 = __ldg(&g_C[A.j0]);  A.C1 = __ldg(&g_C[A.j1]);   // L1-hot table
    B.C0 = __ldg(&g_C[B.j0]);  B.C1 = __ldg(&g_C[B.j1]);

    // preambles
    float4 AaA = __ldg(&g_AB[rtMA + aA].a);
    float4 AaB = __ldg(&g_AB[rtMB + aB].a);
    Quat qaA = qnormalize(qload(__ldg(&node_quat[rtMA + aA])));
    Quat qaB = qnormalize(qload(__ldg(&node_quat[rtMB + aB])));
    Quat qgA = qnormalize(qload(__ldg(&gs_rot[nA])));
    Quat qgB = qnormalize(qload(__ldg(&gs_rot[nB])));

    float3 gxA = { __ldg(&gs_xyz[3 * nA]), __ldg(&gs_xyz[3 * nA + 1]), __ldg(&gs_xyz[3 * nA + 2]) };
    float3 gxB = { __ldg(&gs_xyz[3 * nB]), __ldg(&gs_xyz[3 * nB + 1]), __ldg(&gs_xyz[3 * nB + 2]) };
    float3 xrA = qrot(qaA, gxA);
    float3 xrB = qrot(qaB, gxB);
    float3 xwA = { xrA.x + AaA.x, xrA.y + AaA.y, xrA.z + AaA.z };
    float3 xwB = { xrB.x + AaB.x, xrB.y + AaB.y, xrB.z + AaB.z };
    A.qag = qmul(qaA, qgA);
    B.qag = qmul(qaB, qgB);

    // weights + rotated diffs
    {
        float3 d0 = { xwA.x - A0a.x, xwA.y - A0a.y, xwA.z - A0a.z };
        float3 d1 = { xwA.x - A1a.x, xwA.y - A1a.y, xwA.z - A1a.z };
        float3 e0 = { xwB.x - A0b.x, xwB.y - A0b.y, xwB.z - A0b.z };
        float3 e1 = { xwB.x - A1b.x, xwB.y - A1b.y, xwB.z - A1b.z };
        A.w0 = __expf(-(d0.x * d0.x + d0.y * d0.y + d0.z * d0.z) * A0a.w);
        A.w1 = __expf(-(d1.x * d1.x + d1.y * d1.y + d1.z * d1.z) * A1a.w);
        B.w0 = __expf(-(e0.x * e0.x + e0.y * e0.y + e0.z * e0.z) * A0b.w);
        B.w1 = __expf(-(e1.x * e1.x + e1.y * e1.y + e1.z * e1.z) * A1b.w);
        A.q0.w = B0a.x; A.q0.x = B0a.y; A.q0.y = B0a.z; A.q0.z = B0a.w;
        A.q1.w = B1a.x; A.q1.x = B1a.y; A.q1.y = B1a.z; A.q1.z = B1a.w;
        B.q0.w = B0b.x; B.q0.x = B0b.y; B.q0.y = B0b.z; B.q0.z = B0b.w;
        B.q1.w = B1b.x; B.q1.x = B1b.y; B.q1.y = B1b.z; B.q1.z = B1b.w;
        A.m0 = qrot(A.q0, d0);
        A.m1 = qrot(A.q1, d1);
        B.m0 = qrot(B.q0, e0);
        B.m1 = qrot(B.q1, e1);
    }

    // ---- reductions: 16 butterflies serve 8 gaussians ----
    float SA   = qw_sum(A.w0 + A.w1);
    float SB   = qw_sum(B.w0 + B.w1);
    float muxA = qw_sum(A.w0 * (A.m0.x + A.C0.x) + A.w1 * (A.m1.x + A.C1.x));
    float muxB = qw_sum(B.w0 * (B.m0.x + B.C0.x) + B.w1 * (B.m1.x + B.C1.x));
    float muyA = qw_sum(A.w0 * (A.m0.y + A.C0.y) + A.w1 * (A.m1.y + A.C1.y));
    float muyB = qw_sum(B.w0 * (B.m0.y + B.C0.y) + B.w1 * (B.m1.y + B.C1.y));
    float muzA = qw_sum(A.w0 * (A.m0.z + A.C0.z) + A.w1 * (A.m1.z + A.C1.z));
    float muzB = qw_sum(B.w0 * (B.m0.z + B.C0.z) + B.w1 * (B.m1.z + B.C1.z));
    float qbwA = qw_sum(A.w0 * A.q0.w + A.w1 * A.q1.w);
    float qbwB = qw_sum(B.w0 * B.q0.w + B.w1 * B.q1.w);
    float qbxA = qw_sum(A.w0 * A.q0.x + A.w1 * A.q1.x);
    float qbxB = qw_sum(B.w0 * B.q0.x + B.w1 * B.q1.x);
    float qbyA = qw_sum(A.w0 * A.q0.y + A.w1 * A.q1.y);
    float qbyB = qw_sum(B.w0 * B.q0.y + B.w1 * B.q1.y);
    float qbzA = qw_sum(A.w0 * A.q0.z + A.w1 * A.q1.z);
    float qbzB = qw_sum(B.w0 * B.q0.z + B.w1 * B.q1.z);

    float invSA = 1.f / (SA + EPSV);
    float invSB = 1.f / (SB + EPSV);

    // ---- sem blend: both gaussians interleaved (4 independent loads/iter) ----
    const int src_base = lane & 24;
    float4 saccA = make_float4(0.f, 0.f, 0.f, 0.f);
    float4 saccB = make_float4(0.f, 0.f, 0.f, 0.f);
    #pragma unroll
    for (int k = 0; k < 8; k++) {
        float wkA0 = __shfl_sync(0xffffffffu, A.w0, src_base | k);
        int   jkA0 = __shfl_sync(0xffffffffu, A.j0, src_base | k);
        float wkA1 = __shfl_sync(0xffffffffu, A.w1, src_base | k);
        int   jkA1 = __shfl_sync(0xffffffffu, A.j1, src_base | k);
        float wkB0 = __shfl_sync(0xffffffffu, B.w0, src_base | k);
        int   jkB0 = __shfl_sync(0xffffffffu, B.j0, src_base | k);
        float wkB1 = __shfl_sync(0xffffffffu, B.w1, src_base | k);
        int   jkB1 = __shfl_sync(0xffffffffu, B.j1, src_base | k);
        float4 vA0 = __ldg(&node_sem4[(long)jkA0 * (FSEM / 4) + kl]);
        float4 vA1 = __ldg(&node_sem4[(long)jkA1 * (FSEM / 4) + kl]);
        float4 vB0 = __ldg(&node_sem4[(long)jkB0 * (FSEM / 4) + kl]);
        float4 vB1 = __ldg(&node_sem4[(long)jkB1 * (FSEM / 4) + kl]);
        saccA.x += wkA0 * vA0.x + wkA1 * vA1.x;
        saccA.y += wkA0 * vA0.y + wkA1 * vA1.y;
        saccA.z += wkA0 * vA0.z + wkA1 * vA1.z;
        saccA.w += wkA0 * vA0.w + wkA1 * vA1.w;
        saccB.x += wkB0 * vB0.x + wkB1 * vB1.x;
        saccB.y += wkB0 * vB0.y + wkB1 * vB1.y;
        saccB.z += wkB0 * vB0.z + wkB1 * vB1.z;
        saccB.w += wkB0 * vB0.w + wkB1 * vB1.w;
    }

    float*  o_mu  = out;
    float*  o_fr  = out + 3L  * N;
    float4* o_sem = (float4*)(out + 28L * N);

    // ---- epilogues SEQUENTIALLY (A then B) to cap register pressure ----
    #pragma unroll
    for (int s = 0; s < 2; s++) {
        const int   n    = s ? nB : nA;
        const float invS = s ? invSB : invSA;
        const float qbw  = s ? qbwB : qbwA;
        const float qbx  = s ? qbxB : qbxA;
        const float qby  = s ? qbyB : qbyA;
        const float qbz  = s ? qbzB : qbzA;
        const float mux  = s ? muxB : muxA;
        const float muy  = s ? muyB : muyA;
        const float muz  = s ? muzB : muzA;
        const Quat  qag  = s ? B.qag : A.qag;
        const float4 sacc = s ? saccB : saccA;

        // invS BEFORE normalize is load-bearing (R2 failure); explicit Rb@Rw is
        // clip-safe for degenerate rows (R8 failure).
        Quat qbn; qbn.w = qbw * invS; qbn.x = qbx * invS; qbn.y = qby * invS; qbn.z = qbz * invS;
        qbn = qnormalize(qbn);
        float Rb[3][3]; q2R(qbn, Rb);
        float Rw[3][3]; q2R(qag, Rw);
        float Fr[3][3]; mat3mul(Rb, Rw, Fr);

        float muv = (kl == 0) ? mux : ((kl == 1) ? muy : muz);
        if (kl < 3) o_mu[3 * n + kl] = muv * invS;

        float frv = Fr[0][0];
        frv = (kl == 1) ? Fr[0][1] : frv;
        frv = (kl == 2) ? Fr[0][2] : frv;
        frv = (kl == 3) ? Fr[1][0] : frv;
        frv = (kl == 4) ? Fr[1][1] : frv;
        frv = (kl == 5) ? Fr[1][2] : frv;
        frv = (kl == 6) ? Fr[2][0] : frv;
        frv = (kl == 7) ? Fr[2][1] : frv;
        o_fr[9 * n + kl] = frv;
        if (kl == 0) o_fr[9 * n + 8] = Fr[2][2];

        float4 sv; sv.x = sacc.x * invS; sv.y = sacc.y * invS;
        sv.z = sacc.z * invS; sv.w = sacc.w * invS;
        o_sem[(long)n * (FSEM / 4) + kl] = sv;
    }
}

// ---- elementwise outputs: s, o, sph — float4 vectorized ----
__global__ void __launch_bounds__(256)
dyn_scf_elem_kernel(
    const float4* __restrict__ gs_scal4,
    const float4* __restrict__ gs_op4,
    const float*  __restrict__ feat_dc,
    const float*  __restrict__ feat_rest,
    float*        __restrict__ out,
    int N)
{
    long e = (long)blockIdx.x * blockDim.x + threadIdx.x;
    const long ns4 = 3L * N / 4;
    const long no4 = (long)N / 4;
    float4* o_s4   = (float4*)(out + 12L * N);
    float4* o_o4   = (float4*)(out + 15L * N);
    float4* o_sph4 = (float4*)(out + 16L * N);

    if (e < ns4) {
        float4 v = __ldg(&gs_scal4[e]);
        v.x = 0.1f * sigmoidf(v.x); v.y = 0.1f * sigmoidf(v.y);
        v.z = 0.1f * sigmoidf(v.z); v.w = 0.1f * sigmoidf(v.w);
        o_s4[e] = v;
    } else if (e < ns4 + no4) {
        long i = e - ns4;
        float4 v = __ldg(&gs_op4[i]);
        v.x = sigmoidf(v.x); v.y = sigmoidf(v.y);
        v.z = sigmoidf(v.z); v.w = sigmoidf(v.w);
        o_o4[i] = v;
    } else if (e < ns4 + no4 + 3L * N) {
        long s4 = e - ns4 - no4;
        int n = (int)(s4 / 3);
        int r = (int)(s4 - 3L * n);
        float4 v;
        const float* dc = feat_dc + 3 * n;
        const float* fr = feat_rest + 9 * n;
        if (r == 0) {
            v.x = __ldg(&dc[0]); v.y = __ldg(&dc[1]); v.z = __ldg(&dc[2]); v.w = __ldg(&fr[0]);
        } else if (r == 1) {
            v.x = __ldg(&fr[1]); v.y = __ldg(&fr[2]); v.z = __ldg(&fr[3]); v.w = __ldg(&fr[4]);
        } else {
            v.x = __ldg(&fr[5]); v.y = __ldg(&fr[6]); v.z = __ldg(&fr[7]); v.w = __ldg(&fr[8]);
        }
        o_sph4[s4] = v;
    }
}

extern "C" void kernel_launch(void* const* d_in, const int* in_sizes, int n_in,
                              void* d_out, int out_size) {
    const float*  gs_xyz     = (const float*)d_in[0];
    const float4* gs_rot     = (const float4*)d_in[1];
    const float4* gs_scal4   = (const float4*)d_in[2];
    const float4* gs_op4     = (const float4*)d_in[3];
    const float*  feat_dc    = (const float*)d_in[4];
    const float*  feat_rest  = (const float*)d_in[5];
    const float*  node_xyz   = (const float*)d_in[6];
    const float4* node_quat  = (const float4*)d_in[7];
    const float*  node_sigma = (const float*)d_in[8];
    const float4* node_sem4  = (const float4*)d_in[9];
    const int*    attach     = (const int*)d_in[10];
    const int*    ref_time   = (const int*)d_in[11];
    const int2*   topo2      = (const int2*)d_in[12];
    const int*    t_ptr      = (const int*)d_in[13];

    int N = in_sizes[0] / 3;

    long total4 = (3L * N) / 4 + (long)N / 4 + 3L * N;
    int eblocks = (int)((total4 + 255) / 256);
    dyn_scf_elem_kernel<<<eblocks, 256>>>(
        gs_scal4, gs_op4, feat_dc, feat_rest, (float*)d_out, N);

    int pblocks = (T_STEPS * M_NODES + 255) / 256;
    dyn_scf_pre_kernel<<<pblocks, 256>>>(node_xyz, node_quat, node_sigma, t_ptr);

    // main: 8 gaussians/warp, 8 warps/block -> 64 gaussians per block
    int blocks = (N + 63) / 64;
    dyn_scf_qw_kernel<<<blocks, 256>>>(
        gs_xyz, gs_rot, node_quat, node_sem4,
        attach, ref_time, topo2, (float*)d_out, N);
}

// round 13
// speedup vs baseline: 1.1812x; 1.1812x over previous
#include <cuda_runtime.h>
#include <cuda_bf16.h>

#define M_NODES 10000
#define T_STEPS 40
#define KNN     16
#define FSEM    32
#define EPSV    1e-8f

// Merged (tt,j)-indexed record: 32B aligned, a+b in one 32B sector of one line.
// a = (pref.xyz, 1/(2 sig^2+eps)); b = q_rel.
struct __align__(32) ABRec { float4 a, b; };
__device__ ABRec  g_AB[T_STEPS * M_NODES];   // 12.8 MB, L2-resident
__device__ float4 g_C[M_NODES];              // 160 KB -> L1-resident (p_live.xyz, 0)

struct Quat { float w, x, y, z; };

__device__ __forceinline__ Quat qnormalize(Quat q) {
    float n2 = q.w * q.w + q.x * q.x + q.y * q.y + q.z * q.z;
    float inv = rsqrtf(fmaxf(n2, 1e-24f));   // matches reference clip(norm,1e-12)
    Quat r; r.w = q.w * inv; r.x = q.x * inv; r.y = q.y * inv; r.z = q.z * inv;
    return r;
}

__device__ __forceinline__ Quat qload(float4 v) {
    Quat q; q.w = v.x; q.x = v.y; q.y = v.z; q.z = v.w; return q;
}

__device__ __forceinline__ Quat qmul(Quat a, Quat b) {
    Quat r;
    r.w = a.w * b.w - a.x * b.x - a.y * b.y - a.z * b.z;
    r.x = a.w * b.x + a.x * b.w + a.y * b.z - a.z * b.y;
    r.y = a.w * b.y - a.x * b.z + a.y * b.w + a.z * b.x;
    r.z = a.w * b.z + a.x * b.y - a.y * b.x + a.z * b.w;
    return r;
}

// RAW q2R (no internal normalize): for q ~ 0 yields ~I (reference degenerate path).
__device__ __forceinline__ void q2R(Quat q, float R[3][3]) {
    float w = q.w, x = q.x, y = q.y, z = q.z;
    R[0][0] = 1.f - 2.f * (y * y + z * z);
    R[0][1] = 2.f * (x * y - w * z);
    R[0][2] = 2.f * (x * z + w * y);
    R[1][0] = 2.f * (x * y + w * z);
    R[1][1] = 1.f - 2.f * (x * x + z * z);
    R[1][2] = 2.f * (y * z - w * x);
    R[2][0] = 2.f * (x * z - w * y);
    R[2][1] = 2.f * (y * z + w * x);
    R[2][2] = 1.f - 2.f * (x * x + y * y);
}

__device__ __forceinline__ void mat3mul(const float A[3][3], const float B[3][3], float C[3][3]) {
    #pragma unroll
    for (int i = 0; i < 3; i++)
        #pragma unroll
        for (int j = 0; j < 3; j++)
            C[i][j] = A[i][0] * B[0][j] + A[i][1] * B[1][j] + A[i][2] * B[2][j];
}

__device__ __forceinline__ float3 qrot(Quat q, float3 v) {
    float tx = 2.f * (q.y * v.z - q.z * v.y);
    float ty = 2.f * (q.z * v.x - q.x * v.z);
    float tz = 2.f * (q.x * v.y - q.y * v.x);
    float3 r;
    r.x = v.x + q.w * tx + (q.y * tz - q.z * ty);
    r.y = v.y + q.w * ty + (q.z * tx - q.x * tz);
    r.z = v.z + q.w * tz + (q.x * ty - q.y * tx);
    return r;
}

__device__ __forceinline__ float sigmoidf(float x) {
    return 1.f / (1.f + __expf(-x));
}

__device__ __forceinline__ float qw_sum(float v) {
    v += __shfl_xor_sync(0xffffffffu, v, 4);
    v += __shfl_xor_sync(0xffffffffu, v, 2);
    v += __shfl_xor_sync(0xffffffffu, v, 1);
    return v;
}

// ---- precompute kernel: one thread per (tt, j) ----
__global__ void __launch_bounds__(256)
dyn_scf_pre_kernel(
    const float*  __restrict__ node_xyz,
    const float4* __restrict__ node_quat,
    const float*  __restrict__ node_sigma,
    const int*    __restrict__ t_ptr)
{
    int idx = blockIdx.x * blockDim.x + threadIdx.x;
    if (idx >= T_STEPS * M_NODES) return;
    int j  = idx % M_NODES;
    int tt = idx / M_NODES;
    int t  = __ldg(t_ptr);
    long tMj = (long)t * M_NODES + j;

    Quat qr = qnormalize(qload(__ldg(&node_quat[idx])));
    Quat ql = qnormalize(qload(__ldg(&node_quat[tMj])));
    // q_rel = ql * conj(qr)
    float4 B;
    B.x =  ql.w * qr.w + ql.x * qr.x + ql.y * qr.y + ql.z * qr.z;
    B.y = -ql.w * qr.x + ql.x * qr.w - ql.y * qr.z + ql.z * qr.y;
    B.z = -ql.w * qr.y + ql.x * qr.z + ql.y * qr.w - ql.z * qr.x;
    B.w = -ql.w * qr.z - ql.x * qr.y + ql.y * qr.x + ql.z * qr.w;

    float sig = __ldg(&node_sigma[j]);
    float px = __ldg(&node_xyz[3L * idx]);
    float py = __ldg(&node_xyz[3L * idx + 1]);
    float pz = __ldg(&node_xyz[3L * idx + 2]);

    g_AB[idx].a = make_float4(px, py, pz, 1.f / (2.f * sig * sig + EPSV));
    g_AB[idx].b = B;
    if (tt == t) g_C[j] = make_float4(px, py, pz, 0.f);
}

// ---- FUSED kernel: blocks [0, main_blocks) run the skinning path (identical to
// the 72.2us R11 kernel); blocks [main_blocks, main_blocks+elem_blocks) run the
// elementwise s/o/sph path. Elem blocks fill the stall slack of the
// latency-bound main blocks (DRAM was at 2%) -> near-free.
__global__ void __launch_bounds__(256)
dyn_scf_fused_kernel(
    const float*  __restrict__ gs_xyz,     // (N,3)
    const float4* __restrict__ gs_rot,     // (N,4)
    const float4* __restrict__ node_quat,  // (T,M,4)
    const float4* __restrict__ node_sem4,  // (M,32) as M x 8 float4
    const int*    __restrict__ attach,     // (N,)
    const int*    __restrict__ ref_time,   // (N,)
    const int2*   __restrict__ topo2,      // (M,K) as M x 8 int2
    const float4* __restrict__ gs_scal4,   // (N,3) as 3N/4 float4
    const float4* __restrict__ gs_op4,     // (N,)  as N/4 float4
    const float*  __restrict__ feat_dc,    // (N,3)
    const float*  __restrict__ feat_rest,  // (N,9)
    float*        __restrict__ out,
    int N, int main_blocks)
{
    if (blockIdx.x >= main_blocks) {
        // ================= elem path =================
        long e = (long)(blockIdx.x - main_blocks) * blockDim.x + threadIdx.x;
        const long ns4 = 3L * N / 4;
        const long no4 = (long)N / 4;
        float4* o_s4   = (float4*)(out + 12L * N);
        float4* o_o4   = (float4*)(out + 15L * N);
        float4* o_sph4 = (float4*)(out + 16L * N);

        if (e < ns4) {
            float4 v = __ldg(&gs_scal4[e]);
            v.x = 0.1f * sigmoidf(v.x); v.y = 0.1f * sigmoidf(v.y);
            v.z = 0.1f * sigmoidf(v.z); v.w = 0.1f * sigmoidf(v.w);
            o_s4[e] = v;
        } else if (e < ns4 + no4) {
            long i = e - ns4;
            float4 v = __ldg(&gs_op4[i]);
            v.x = sigmoidf(v.x); v.y = sigmoidf(v.y);
            v.z = sigmoidf(v.z); v.w = sigmoidf(v.w);
            o_o4[i] = v;
        } else if (e < ns4 + no4 + 3L * N) {
            long s4 = e - ns4 - no4;
            int n = (int)(s4 / 3);
            int r = (int)(s4 - 3L * n);
            float4 v;
            const float* dc = feat_dc + 3 * n;
            const float* fr = feat_rest + 9 * n;
            if (r == 0) {
                v.x = __ldg(&dc[0]); v.y = __ldg(&dc[1]); v.z = __ldg(&dc[2]); v.w = __ldg(&fr[0]);
            } else if (r == 1) {
                v.x = __ldg(&fr[1]); v.y = __ldg(&fr[2]); v.z = __ldg(&fr[3]); v.w = __ldg(&fr[4]);
            } else {
                v.x = __ldg(&fr[5]); v.y = __ldg(&fr[6]); v.z = __ldg(&fr[7]); v.w = __ldg(&fr[8]);
            }
            o_sph4[s4] = v;
        }
        return;
    }

    // ================= main skinning path (identical to R11 72.2us kernel) ======
    const int lane = threadIdx.x & 31;
    const int kl   = lane & 7;
    const int grp  = (lane >> 3) & 3;
    const long warp_gid = (long)blockIdx.x * (blockDim.x >> 5) + (threadIdx.x >> 5);
    const int n = (int)(warp_gid * 4 + grp);
    if (n >= N) return;   // N % 32 == 0 -> warps never partial

    const int a  = __ldg(&attach[n]);
    const int rt = __ldg(&ref_time[n]);
    const long rtM = (long)rt * M_NODES;

    // topo: one coalesced int2 per lane covers k = 2kl, 2kl+1 (sum order irrelevant)
    const int2 jj = __ldg(&topo2[a * (KNN / 2) + kl]);
    const int j0 = jj.x, j1 = jj.y;

    // ---- k-phase gathers issued early (overlap preamble math with their latency) ----
    const ABRec* P0 = &g_AB[rtM + j0];
    const ABRec* P1 = &g_AB[rtM + j1];
    float4 A0 = __ldg(&P0->a);
    float4 A1 = __ldg(&P1->a);
    float4 B0 = __ldg(&P0->b);
    float4 B1 = __ldg(&P1->b);
    float4 C0 = __ldg(&g_C[j0]);   // 160KB table: near-always L1-hit
    float4 C1 = __ldg(&g_C[j1]);

    // ---- preamble: quaternion-only ----
    float4 Aa = __ldg(&g_AB[rtM + a].a);
    Quat qa = qnormalize(qload(__ldg(&node_quat[rtM + a])));
    Quat qg = qnormalize(qload(__ldg(&gs_rot[n])));

    float3 gx = { __ldg(&gs_xyz[3 * n]), __ldg(&gs_xyz[3 * n + 1]), __ldg(&gs_xyz[3 * n + 2]) };
    float3 xr = qrot(qa, gx);
    float3 xw = { xr.x + Aa.x, xr.y + Aa.y, xr.z + Aa.z };

    Quat qag = qmul(qa, qg);   // unit*unit -> unit; R_world = R(qag)

    float3 d0 = { xw.x - A0.x, xw.y - A0.y, xw.z - A0.z };
    float3 d1 = { xw.x - A1.x, xw.y - A1.y, xw.z - A1.z };
    float w0 = __expf(-(d0.x * d0.x + d0.y * d0.y + d0.z * d0.z) * A0.w);
    float w1 = __expf(-(d1.x * d1.x + d1.y * d1.y + d1.z * d1.z) * A1.w);

    Quat q0; q0.w = B0.x; q0.x = B0.y; q0.y = B0.z; q0.z = B0.w;
    Quat q1; q1.w = B1.x; q1.x = B1.y; q1.y = B1.z; q1.z = B1.w;
    float3 m0 = qrot(q0, d0);
    float3 m1 = qrot(q1, d1);

    // ---- group reductions (serve all 4 gaussians of the warp at once) ----
    float S   = qw_sum(w0 + w1);
    float mux = qw_sum(w0 * (m0.x + C0.x) + w1 * (m1.x + C1.x));
    float muy = qw_sum(w0 * (m0.y + C0.y) + w1 * (m1.y + C1.y));
    float muz = qw_sum(w0 * (m0.z + C0.z) + w1 * (m1.z + C1.z));
    float qbw = qw_sum(w0 * q0.w + w1 * q1.w);
    float qbx = qw_sum(w0 * q0.x + w1 * q1.x);
    float qby = qw_sum(w0 * q0.y + w1 * q1.y);
    float qbz = qw_sum(w0 * q0.z + w1 * q1.z);

    float invS = 1.f / (S + EPSV);

    // ---- sem blend ----
    const int src_base = lane & 24;
    float4 sacc = make_float4(0.f, 0.f, 0.f, 0.f);
    #pragma unroll
    for (int k = 0; k < 8; k++) {
        float wk = __shfl_sync(0xffffffffu, w0, src_base | k);
        int   jk = __shfl_sync(0xffffffffu, j0, src_base | k);
        float4 v = __ldg(&node_sem4[(long)jk * (FSEM / 4) + kl]);
        sacc.x += wk * v.x; sacc.y += wk * v.y; sacc.z += wk * v.z; sacc.w += wk * v.w;
    }
    #pragma unroll
    for (int k = 0; k < 8; k++) {
        float wk = __shfl_sync(0xffffffffu, w1, src_base | k);
        int   jk = __shfl_sync(0xffffffffu, j1, src_base | k);
        float4 v = __ldg(&node_sem4[(long)jk * (FSEM / 4) + kl]);
        sacc.x += wk * v.x; sacc.y += wk * v.y; sacc.z += wk * v.z; sacc.w += wk * v.w;
    }

    // ---- frame epilogue: EXPLICIT Rb @ Rw (clip-safe; see R8 failure).
    // invS scaling BEFORE normalize is load-bearing (R2 failure): for clipped rows
    // qbn ~ 0 -> Rb ~ I -> Fr = Rw, which quaternion composition would NOT give.
    Quat qbn; qbn.w = qbw * invS; qbn.x = qbx * invS; qbn.y = qby * invS; qbn.z = qbz * invS;
    qbn = qnormalize(qbn);
    float Rb[3][3]; q2R(qbn, Rb);
    float Rw[3][3]; q2R(qag, Rw);
    float Fr[3][3]; mat3mul(Rb, Rw, Fr);

    // ---- outputs ----
    float*  o_mu  = out;
    float*  o_fr  = out + 3L  * N;
    float4* o_sem = (float4*)(out + 28L * N);

    float muv = (kl == 0) ? mux : ((kl == 1) ? muy : muz);
    if (kl < 3) o_mu[3 * n + kl] = muv * invS;

    float frv = Fr[0][0];
    frv = (kl == 1) ? Fr[0][1] : frv;
    frv = (kl == 2) ? Fr[0][2] : frv;
    frv = (kl == 3) ? Fr[1][0] : frv;
    frv = (kl == 4) ? Fr[1][1] : frv;
    frv = (kl == 5) ? Fr[1][2] : frv;
    frv = (kl == 6) ? Fr[2][0] : frv;
    frv = (kl == 7) ? Fr[2][1] : frv;
    o_fr[9 * n + kl] = frv;
    if (kl == 0) o_fr[9 * n + 8] = Fr[2][2];

    float4 sv; sv.x = sacc.x * invS; sv.y = sacc.y * invS;
    sv.z = sacc.z * invS; sv.w = sacc.w * invS;
    o_sem[(long)n * (FSEM / 4) + kl] = sv;
}

extern "C" void kernel_launch(void* const* d_in, const int* in_sizes, int n_in,
                              void* d_out, int out_size) {
    const float*  gs_xyz     = (const float*)d_in[0];
    const float4* gs_rot     = (const float4*)d_in[1];
    const float4* gs_scal4   = (const float4*)d_in[2];
    const float4* gs_op4     = (const float4*)d_in[3];
    const float*  feat_dc    = (const float*)d_in[4];
    const float*  feat_rest  = (const float*)d_in[5];
    const float*  node_xyz   = (const float*)d_in[6];
    const float4* node_quat  = (const float4*)d_in[7];
    const float*  node_sigma = (const float*)d_in[8];
    const float4* node_sem4  = (const float4*)d_in[9];
    const int*    attach     = (const int*)d_in[10];
    const int*    ref_time   = (const int*)d_in[11];
    const int2*   topo2      = (const int2*)d_in[12];
    const int*    t_ptr      = (const int*)d_in[13];

    int N = in_sizes[0] / 3;

    // 1) table precompute (main path depends on it; elem path does not, but
    //    the fused kernel runs after anyway)
    int pblocks = (T_STEPS * M_NODES + 255) / 256;
    dyn_scf_pre_kernel<<<pblocks, 256>>>(node_xyz, node_quat, node_sigma, t_ptr);

    // 2) fused main + elem
    int main_blocks = (N + 31) / 32;                       // 4 gaussians/warp, 8 warps/block
    long total4 = (3L * N) / 4 + (long)N / 4 + 3L * N;     // elem float4 units
    int elem_blocks = (int)((total4 + 255) / 256);
    dyn_scf_fused_kernel<<<main_blocks + elem_blocks, 256>>>(
        gs_xyz, gs_rot, node_quat, node_sem4,
        attach, ref_time, topo2,
        gs_scal4, gs_op4, feat_dc, feat_rest,
        (float*)d_out, N, main_blocks);
}

// round 14
// speedup vs baseline: 1.2073x; 1.0221x over previous
#include <cuda_runtime.h>
#include <cuda_bf16.h>

#define M_NODES 10000
#define T_STEPS 40
#define KNN     16
#define FSEM    32
#define EPSV    1e-8f

// Merged (tt,j)-indexed record: 32B aligned, a+b in one 32B sector of one line.
// a = (pref.xyz, 1/(2 sig^2+eps)); b = q_rel.
struct __align__(32) ABRec { float4 a, b; };
__device__ ABRec  g_AB[T_STEPS * M_NODES];   // 12.8 MB, L2-resident
__device__ float4 g_C[M_NODES];              // 160 KB -> L1-resident (p_live.xyz, 0)

struct Quat { float w, x, y, z; };

__device__ __forceinline__ Quat qnormalize(Quat q) {
    float n2 = q.w * q.w + q.x * q.x + q.y * q.y + q.z * q.z;
    float inv = rsqrtf(fmaxf(n2, 1e-24f));   // matches reference clip(norm,1e-12)
    Quat r; r.w = q.w * inv; r.x = q.x * inv; r.y = q.y * inv; r.z = q.z * inv;
    return r;
}

__device__ __forceinline__ Quat qload(float4 v) {
    Quat q; q.w = v.x; q.x = v.y; q.y = v.z; q.z = v.w; return q;
}

__device__ __forceinline__ Quat qmul(Quat a, Quat b) {
    Quat r;
    r.w = a.w * b.w - a.x * b.x - a.y * b.y - a.z * b.z;
    r.x = a.w * b.x + a.x * b.w + a.y * b.z - a.z * b.y;
    r.y = a.w * b.y - a.x * b.z + a.y * b.w + a.z * b.x;
    r.z = a.w * b.z + a.x * b.y - a.y * b.x + a.z * b.w;
    return r;
}

// RAW q2R (no internal normalize): for q ~ 0 yields ~I (reference degenerate path).
__device__ __forceinline__ void q2R(Quat q, float R[3][3]) {
    float w = q.w, x = q.x, y = q.y, z = q.z;
    R[0][0] = 1.f - 2.f * (y * y + z * z);
    R[0][1] = 2.f * (x * y - w * z);
    R[0][2] = 2.f * (x * z + w * y);
    R[1][0] = 2.f * (x * y + w * z);
    R[1][1] = 1.f - 2.f * (x * x + z * z);
    R[1][2] = 2.f * (y * z - w * x);
    R[2][0] = 2.f * (x * z - w * y);
    R[2][1] = 2.f * (y * z + w * x);
    R[2][2] = 1.f - 2.f * (x * x + y * y);
}

__device__ __forceinline__ void mat3mul(const float A[3][3], const float B[3][3], float C[3][3]) {
    #pragma unroll
    for (int i = 0; i < 3; i++)
        #pragma unroll
        for (int j = 0; j < 3; j++)
            C[i][j] = A[i][0] * B[0][j] + A[i][1] * B[1][j] + A[i][2] * B[2][j];
}

__device__ __forceinline__ float3 qrot(Quat q, float3 v) {
    float tx = 2.f * (q.y * v.z - q.z * v.y);
    float ty = 2.f * (q.z * v.x - q.x * v.z);
    float tz = 2.f * (q.x * v.y - q.y * v.x);
    float3 r;
    r.x = v.x + q.w * tx + (q.y * tz - q.z * ty);
    r.y = v.y + q.w * ty + (q.z * tx - q.x * tz);
    r.z = v.z + q.w * tz + (q.x * ty - q.y * tx);
    return r;
}

__device__ __forceinline__ float sigmoidf(float x) {
    return 1.f / (1.f + __expf(-x));
}

__device__ __forceinline__ float qw_sum(float v) {
    v += __shfl_xor_sync(0xffffffffu, v, 4);
    v += __shfl_xor_sync(0xffffffffu, v, 2);
    v += __shfl_xor_sync(0xffffffffu, v, 1);
    return v;
}

// ---- precompute kernel: one thread per (tt, j) ----
__global__ void __launch_bounds__(256)
dyn_scf_pre_kernel(
    const float*  __restrict__ node_xyz,
    const float4* __restrict__ node_quat,
    const float*  __restrict__ node_sigma,
    const int*    __restrict__ t_ptr)
{
    int idx = blockIdx.x * blockDim.x + threadIdx.x;
    if (idx >= T_STEPS * M_NODES) return;
    int j  = idx % M_NODES;
    int tt = idx / M_NODES;
    int t  = __ldg(t_ptr);
    long tMj = (long)t * M_NODES + j;

    Quat qr = qnormalize(qload(__ldg(&node_quat[idx])));
    Quat ql = qnormalize(qload(__ldg(&node_quat[tMj])));
    // q_rel = ql * conj(qr)
    float4 B;
    B.x =  ql.w * qr.w + ql.x * qr.x + ql.y * qr.y + ql.z * qr.z;
    B.y = -ql.w * qr.x + ql.x * qr.w - ql.y * qr.z + ql.z * qr.y;
    B.z = -ql.w * qr.y + ql.x * qr.z + ql.y * qr.w - ql.z * qr.x;
    B.w = -ql.w * qr.z - ql.x * qr.y + ql.y * qr.x + ql.z * qr.w;

    float sig = __ldg(&node_sigma[j]);
    float px = __ldg(&node_xyz[3L * idx]);
    float py = __ldg(&node_xyz[3L * idx + 1]);
    float pz = __ldg(&node_xyz[3L * idx + 2]);

    g_AB[idx].a = make_float4(px, py, pz, 1.f / (2.f * sig * sig + EPSV));
    g_AB[idx].b = B;
    if (tt == t) g_C[j] = make_float4(px, py, pz, 0.f);
}

// ---- FUSED kernel: main skinning blocks + elementwise blocks ----
__global__ void __launch_bounds__(256)
dyn_scf_fused_kernel(
    const float*  __restrict__ gs_xyz,     // (N,3)
    const float4* __restrict__ gs_rot,     // (N,4)
    const float4* __restrict__ node_quat,  // (T,M,4)
    const float4* __restrict__ node_sem4,  // (M,32) as M x 8 float4
    const int*    __restrict__ attach,     // (N,)
    const int*    __restrict__ ref_time,   // (N,)
    const int2*   __restrict__ topo2,      // (M,K) as M x 8 int2
    const float4* __restrict__ gs_scal4,   // (N,3) as 3N/4 float4
    const float4* __restrict__ gs_op4,     // (N,)  as N/4 float4
    const float*  __restrict__ feat_dc,    // (N,3)
    const float*  __restrict__ feat_rest,  // (N,9)
    float*        __restrict__ out,
    int N, int main_blocks)
{
    if (blockIdx.x >= main_blocks) {
        // ================= elem path =================
        long e = (long)(blockIdx.x - main_blocks) * blockDim.x + threadIdx.x;
        const long ns4 = 3L * N / 4;
        const long no4 = (long)N / 4;
        float4* o_s4   = (float4*)(out + 12L * N);
        float4* o_o4   = (float4*)(out + 15L * N);
        float4* o_sph4 = (float4*)(out + 16L * N);

        if (e < ns4) {
            float4 v = __ldg(&gs_scal4[e]);
            v.x = 0.1f * sigmoidf(v.x); v.y = 0.1f * sigmoidf(v.y);
            v.z = 0.1f * sigmoidf(v.z); v.w = 0.1f * sigmoidf(v.w);
            o_s4[e] = v;
        } else if (e < ns4 + no4) {
            long i = e - ns4;
            float4 v = __ldg(&gs_op4[i]);
            v.x = sigmoidf(v.x); v.y = sigmoidf(v.y);
            v.z = sigmoidf(v.z); v.w = sigmoidf(v.w);
            o_o4[i] = v;
        } else if (e < ns4 + no4 + 3L * N) {
            long s4 = e - ns4 - no4;
            int n = (int)(s4 / 3);
            int r = (int)(s4 - 3L * n);
            float4 v;
            const float* dc = feat_dc + 3 * n;
            const float* fr = feat_rest + 9 * n;
            if (r == 0) {
                v.x = __ldg(&dc[0]); v.y = __ldg(&dc[1]); v.z = __ldg(&dc[2]); v.w = __ldg(&fr[0]);
            } else if (r == 1) {
                v.x = __ldg(&fr[1]); v.y = __ldg(&fr[2]); v.z = __ldg(&fr[3]); v.w = __ldg(&fr[4]);
            } else {
                v.x = __ldg(&fr[5]); v.y = __ldg(&fr[6]); v.z = __ldg(&fr[7]); v.w = __ldg(&fr[8]);
            }
            o_sph4[s4] = v;
        }
        return;
    }

    // ================= main skinning path =================
    const int lane = threadIdx.x & 31;
    const int kl   = lane & 7;
    const int grp  = (lane >> 3) & 3;
    const long warp_gid = (long)blockIdx.x * (blockDim.x >> 5) + (threadIdx.x >> 5);
    const int n = (int)(warp_gid * 4 + grp);
    if (n >= N) return;   // N % 32 == 0 -> warps never partial

    const int a  = __ldg(&attach[n]);
    const int rt = __ldg(&ref_time[n]);
    const long rtM = (long)rt * M_NODES;

    // lane kl OWNS records 2kl (j0=jj.x) and 2kl+1 (j1=jj.y); record r = topo[a*16+r]
    const int2 jj = __ldg(&topo2[a * (KNN / 2) + kl]);

    const int base = lane & 24;        // group base lane (absolute)
    const int hf   = kl & 1;           // 0: load a-half, 1: load b-half
    const int comp = (kl >> 1) & 1;    // j component of my load-record
    const int quad = kl >> 2;          // owner offset within instruction

    // ---- pair-cooperative AB gather: load instr m covers records 4m..4m+3;
    // lane kl loads half hf of record r = 4m + (kl>>1); owner lane of r = 2m + quad.
    // Pairs share the record's 128B line -> 16 distinct lines/instr instead of 32.
    const float4* AB4 = (const float4*)g_AB;   // record j at float4 indices 2j, 2j+1
    int jm[4];
    #pragma unroll
    for (int m = 0; m < 4; m++) {
        int jx = __shfl_sync(0xffffffffu, jj.x, base + 2 * m + quad);
        int jy = __shfl_sync(0xffffffffu, jj.y, base + 2 * m + quad);
        jm[m] = comp ? jy : jx;
    }
    float4 v0 = __ldg(&AB4[(rtM + jm[0]) * 2 + hf]);
    float4 v1 = __ldg(&AB4[(rtM + jm[1]) * 2 + hf]);
    float4 v2 = __ldg(&AB4[(rtM + jm[2]) * 2 + hf]);
    float4 v3 = __ldg(&AB4[(rtM + jm[3]) * 2 + hf]);

    // ---- preamble (overlaps the gathers above) ----
    float4 Aa = __ldg(&AB4[(rtM + a) * 2]);
    Quat qa = qnormalize(qload(__ldg(&node_quat[rtM + a])));
    Quat qg = qnormalize(qload(__ldg(&gs_rot[n])));

    float3 gx = { __ldg(&gs_xyz[3 * n]), __ldg(&gs_xyz[3 * n + 1]), __ldg(&gs_xyz[3 * n + 2]) };
    float3 xr = qrot(qa, gx);
    float3 xw = { xr.x + Aa.x, xr.y + Aa.y, xr.z + Aa.z };
    Quat qag = qmul(qa, qg);   // unit*unit -> unit; R_world = R(qag)

    // ---- per-instruction pair compute. Even lane: w from a-half; odd lane: qrot
    // from b-half with (d, w) shuffled across the pair. Wrong-role garbage is
    // excluded via SEL (ternary), never multiplied (0*inf would NaN-poison).
    float accS = 0.f;
    float3 accMu = { 0.f, 0.f, 0.f };
    Quat accQb = { 0.f, 0.f, 0.f, 0.f };
    float wsav[4];   // valid on even lanes: w of record 4m + kl/2

    #pragma unroll
    for (int m = 0; m < 4; m++) {
        float4 vm = (m == 0) ? v0 : (m == 1) ? v1 : (m == 2) ? v2 : v3;
        // even-lane role
        float3 d = { xw.x - vm.x, xw.y - vm.y, xw.z - vm.z };
        float dsq = d.x * d.x + d.y * d.y + d.z * d.z;
        float w = __expf(-dsq * vm.w);
        wsav[m] = w;
        // pair transfer (even -> odd)
        float dxr = __shfl_xor_sync(0xffffffffu, d.x, 1);
        float dyr = __shfl_xor_sync(0xffffffffu, d.y, 1);
        float dzr = __shfl_xor_sync(0xffffffffu, d.z, 1);
        float wr  = __shfl_xor_sync(0xffffffffu, w,   1);
        // odd-lane role
        Quat q; q.w = vm.x; q.x = vm.y; q.y = vm.z; q.z = vm.w;
        float3 dd = { dxr, dyr, dzr };
        float3 mv = qrot(q, dd);
        float4 Cv = __ldg(&g_C[jm[m]]);   // L1-hot; pair shares the line
        float wro = hf ? wr : 0.f;        // SEL: discards even-lane garbage wr
        float ws  = hf ? 0.f : w;         // SEL: discards odd-lane garbage w
        accS    += ws;
        accMu.x += wro * (mv.x + Cv.x);
        accMu.y += wro * (mv.y + Cv.y);
        accMu.z += wro * (mv.z + Cv.z);
        accQb.w += wro * q.w;
        accQb.x += wro * q.x;
        accQb.y += wro * q.y;
        accQb.z += wro * q.z;
    }

    // ---- group reductions (partials per role; totals complete across 8 lanes) ----
    float S   = qw_sum(accS);
    float mux = qw_sum(accMu.x);
    float muy = qw_sum(accMu.y);
    float muz = qw_sum(accMu.z);
    float qbw = qw_sum(accQb.w);
    float qbx = qw_sum(accQb.x);
    float qby = qw_sum(accQb.y);
    float qbz = qw_sum(accQb.z);

    float invS = 1.f / (S + EPSV);

    // ---- sem blend: record k -> w at (register k>>2, even lane 2*(k&3));
    //                 j at (owner lane k>>1, component k&1) ----
    float4 sacc = make_float4(0.f, 0.f, 0.f, 0.f);
    #pragma unroll
    for (int k = 0; k < KNN; k++) {
        float wk = __shfl_sync(0xffffffffu, wsav[k >> 2], base + 2 * (k & 3));
        int   jk = (k & 1) ? __shfl_sync(0xffffffffu, jj.y, base + (k >> 1))
                           : __shfl_sync(0xffffffffu, jj.x, base + (k >> 1));
        float4 vv = __ldg(&node_sem4[(long)jk * (FSEM / 4) + kl]);
        sacc.x += wk * vv.x; sacc.y += wk * vv.y;
        sacc.z += wk * vv.z; sacc.w += wk * vv.w;
    }

    // ---- frame epilogue: EXPLICIT Rb @ Rw (clip-safe; see R8 failure).
    // invS scaling BEFORE normalize is load-bearing (R2 failure).
    Quat qbn; qbn.w = qbw * invS; qbn.x = qbx * invS; qbn.y = qby * invS; qbn.z = qbz * invS;
    qbn = qnormalize(qbn);
    float Rb[3][3]; q2R(qbn, Rb);
    float Rw[3][3]; q2R(qag, Rw);
    float Fr[3][3]; mat3mul(Rb, Rw, Fr);

    // ---- outputs ----
    float*  o_mu  = out;
    float*  o_fr  = out + 3L  * N;
    float4* o_sem = (float4*)(out + 28L * N);

    float muv = (kl == 0) ? mux : ((kl == 1) ? muy : muz);
    if (kl < 3) o_mu[3 * n + kl] = muv * invS;

    float frv = Fr[0][0];
    frv = (kl == 1) ? Fr[0][1] : frv;
    frv = (kl == 2) ? Fr[0][2] : frv;
    frv = (kl == 3) ? Fr[1][0] : frv;
    frv = (kl == 4) ? Fr[1][1] : frv;
    frv = (kl == 5) ? Fr[1][2] : frv;
    frv = (kl == 6) ? Fr[2][0] : frv;
    frv = (kl == 7) ? Fr[2][1] : frv;
    o_fr[9 * n + kl] = frv;
    if (kl == 0) o_fr[9 * n + 8] = Fr[2][2];

    float4 sv; sv.x = sacc.x * invS; sv.y = sacc.y * invS;
    sv.z = sacc.z * invS; sv.w = sacc.w * invS;
    o_sem[(long)n * (FSEM / 4) + kl] = sv;
}

extern "C" void kernel_launch(void* const* d_in, const int* in_sizes, int n_in,
                              void* d_out, int out_size) {
    const float*  gs_xyz     = (const float*)d_in[0];
    const float4* gs_rot     = (const float4*)d_in[1];
    const float4* gs_scal4   = (const float4*)d_in[2];
    const float4* gs_op4     = (const float4*)d_in[3];
    const float*  feat_dc    = (const float*)d_in[4];
    const float*  feat_rest  = (const float*)d_in[5];
    const float*  node_xyz   = (const float*)d_in[6];
    const float4* node_quat  = (const float4*)d_in[7];
    const float*  node_sigma = (const float*)d_in[8];
    const float4* node_sem4  = (const float4*)d_in[9];
    const int*    attach     = (const int*)d_in[10];
    const int*    ref_time   = (const int*)d_in[11];
    const int2*   topo2      = (const int2*)d_in[12];
    const int*    t_ptr      = (const int*)d_in[13];

    int N = in_sizes[0] / 3;

    // 1) table precompute
    int pblocks = (T_STEPS * M_NODES + 255) / 256;
    dyn_scf_pre_kernel<<<pblocks, 256>>>(node_xyz, node_quat, node_sigma, t_ptr);

    // 2) fused main + elem
    int main_blocks = (N + 31) / 32;                       // 4 gaussians/warp, 8 warps/block
    long total4 = (3L * N) / 4 + (long)N / 4 + 3L * N;     // elem float4 units
    int elem_blocks = (int)((total4 + 255) / 256);
    dyn_scf_fused_kernel<<<main_blocks + elem_blocks, 256>>>(
        gs_xyz, gs_rot, node_quat, node_sem4,
        attach, ref_time, topo2,
        gs_scal4, gs_op4, feat_dc, feat_rest,
        (float*)d_out, N, main_blocks);
}

// round 15
// speedup vs baseline: 1.2148x; 1.0061x over previous
#include <cuda_runtime.h>
#include <cuda_bf16.h>

#define M_NODES 10000
#define T_STEPS 40
#define KNN     16
#define FSEM    32
#define EPSV    1e-8f

// Merged (tt,j)-indexed record: 32B aligned, a+b in one 32B sector of one line.
// a = (pref.xyz, 1/(2 sig^2+eps)); b = q_rel.
struct __align__(32) ABRec { float4 a, b; };
__device__ ABRec  g_AB[T_STEPS * M_NODES];   // 12.8 MB, L2-resident
__device__ float4 g_C[M_NODES];              // 160 KB -> L1-resident (p_live.xyz, 0)

struct Quat { float w, x, y, z; };

__device__ __forceinline__ Quat qnormalize(Quat q) {
    float n2 = q.w * q.w + q.x * q.x + q.y * q.y + q.z * q.z;
    float inv = rsqrtf(fmaxf(n2, 1e-24f));   // matches reference clip(norm,1e-12)
    Quat r; r.w = q.w * inv; r.x = q.x * inv; r.y = q.y * inv; r.z = q.z * inv;
    return r;
}

__device__ __forceinline__ Quat qload(float4 v) {
    Quat q; q.w = v.x; q.x = v.y; q.y = v.z; q.z = v.w; return q;
}

__device__ __forceinline__ Quat qmul(Quat a, Quat b) {
    Quat r;
    r.w = a.w * b.w - a.x * b.x - a.y * b.y - a.z * b.z;
    r.x = a.w * b.x + a.x * b.w + a.y * b.z - a.z * b.y;
    r.y = a.w * b.y - a.x * b.z + a.y * b.w + a.z * b.x;
    r.z = a.w * b.z + a.x * b.y - a.y * b.x + a.z * b.w;
    return r;
}

// RAW q2R (no internal normalize): for q ~ 0 yields ~I (reference degenerate path).
__device__ __forceinline__ void q2R(Quat q, float R[3][3]) {
    float w = q.w, x = q.x, y = q.y, z = q.z;
    R[0][0] = 1.f - 2.f * (y * y + z * z);
    R[0][1] = 2.f * (x * y - w * z);
    R[0][2] = 2.f * (x * z + w * y);
    R[1][0] = 2.f * (x * y + w * z);
    R[1][1] = 1.f - 2.f * (x * x + z * z);
    R[1][2] = 2.f * (y * z - w * x);
    R[2][0] = 2.f * (x * z - w * y);
    R[2][1] = 2.f * (y * z + w * x);
    R[2][2] = 1.f - 2.f * (x * x + y * y);
}

__device__ __forceinline__ void mat3mul(const float A[3][3], const float B[3][3], float C[3][3]) {
    #pragma unroll
    for (int i = 0; i < 3; i++)
        #pragma unroll
        for (int j = 0; j < 3; j++)
            C[i][j] = A[i][0] * B[0][j] + A[i][1] * B[1][j] + A[i][2] * B[2][j];
}

__device__ __forceinline__ float3 qrot(Quat q, float3 v) {
    float tx = 2.f * (q.y * v.z - q.z * v.y);
    float ty = 2.f * (q.z * v.x - q.x * v.z);
    float tz = 2.f * (q.x * v.y - q.y * v.x);
    float3 r;
    r.x = v.x + q.w * tx + (q.y * tz - q.z * ty);
    r.y = v.y + q.w * ty + (q.z * tx - q.x * tz);
    r.z = v.z + q.w * tz + (q.x * ty - q.y * tx);
    return r;
}

__device__ __forceinline__ float sigmoidf(float x) {
    return 1.f / (1.f + __expf(-x));
}

__device__ __forceinline__ float qw_sum(float v) {
    v += __shfl_xor_sync(0xffffffffu, v, 4);
    v += __shfl_xor_sync(0xffffffffu, v, 2);
    v += __shfl_xor_sync(0xffffffffu, v, 1);
    return v;
}

// ---- precompute kernel: one thread per (tt, j) ----
__global__ void __launch_bounds__(256)
dyn_scf_pre_kernel(
    const float*  __restrict__ node_xyz,
    const float4* __restrict__ node_quat,
    const float*  __restrict__ node_sigma,
    const int*    __restrict__ t_ptr)
{
    int idx = blockIdx.x * blockDim.x + threadIdx.x;
    if (idx >= T_STEPS * M_NODES) return;
    int j  = idx % M_NODES;
    int tt = idx / M_NODES;
    int t  = __ldg(t_ptr);
    long tMj = (long)t * M_NODES + j;

    Quat qr = qnormalize(qload(__ldg(&node_quat[idx])));
    Quat ql = qnormalize(qload(__ldg(&node_quat[tMj])));
    // q_rel = ql * conj(qr)
    float4 B;
    B.x =  ql.w * qr.w + ql.x * qr.x + ql.y * qr.y + ql.z * qr.z;
    B.y = -ql.w * qr.x + ql.x * qr.w - ql.y * qr.z + ql.z * qr.y;
    B.z = -ql.w * qr.y + ql.x * qr.z + ql.y * qr.w - ql.z * qr.x;
    B.w = -ql.w * qr.z - ql.x * qr.y + ql.y * qr.x + ql.z * qr.w;

    float sig = __ldg(&node_sigma[j]);
    float px = __ldg(&node_xyz[3L * idx]);
    float py = __ldg(&node_xyz[3L * idx + 1]);
    float pz = __ldg(&node_xyz[3L * idx + 2]);

    g_AB[idx].a = make_float4(px, py, pz, 1.f / (2.f * sig * sig + EPSV));
    g_AB[idx].b = B;
    if (tt == t) g_C[j] = make_float4(px, py, pz, 0.f);
}

// ---- FUSED kernel: main skinning blocks + elementwise blocks ----
// launch_bounds(256, 5): cap regs at ~51 so 5 blocks (40 warps) fit per SM —
// R14 measured 54 regs -> only 4 blocks resident (occ 46%), leaving issue slots idle.
__global__ void __launch_bounds__(256, 5)
dyn_scf_fused_kernel(
    const float*  __restrict__ gs_xyz,     // (N,3)
    const float4* __restrict__ gs_rot,     // (N,4)
    const float4* __restrict__ node_quat,  // (T,M,4)
    const float4* __restrict__ node_sem4,  // (M,32) as M x 8 float4
    const int*    __restrict__ attach,     // (N,)
    const int*    __restrict__ ref_time,   // (N,)
    const int2*   __restrict__ topo2,      // (M,K) as M x 8 int2
    const float4* __restrict__ gs_scal4,   // (N,3) as 3N/4 float4
    const float4* __restrict__ gs_op4,     // (N,)  as N/4 float4
    const float*  __restrict__ feat_dc,    // (N,3)
    const float*  __restrict__ feat_rest,  // (N,9)
    float*        __restrict__ out,
    int N, int main_blocks)
{
    if (blockIdx.x >= main_blocks) {
        // ================= elem path =================
        long e = (long)(blockIdx.x - main_blocks) * blockDim.x + threadIdx.x;
        const long ns4 = 3L * N / 4;
        const long no4 = (long)N / 4;
        float4* o_s4   = (float4*)(out + 12L * N);
        float4* o_o4   = (float4*)(out + 15L * N);
        float4* o_sph4 = (float4*)(out + 16L * N);

        if (e < ns4) {
            float4 v = __ldg(&gs_scal4[e]);
            v.x = 0.1f * sigmoidf(v.x); v.y = 0.1f * sigmoidf(v.y);
            v.z = 0.1f * sigmoidf(v.z); v.w = 0.1f * sigmoidf(v.w);
            o_s4[e] = v;
        } else if (e < ns4 + no4) {
            long i = e - ns4;
            float4 v = __ldg(&gs_op4[i]);
            v.x = sigmoidf(v.x); v.y = sigmoidf(v.y);
            v.z = sigmoidf(v.z); v.w = sigmoidf(v.w);
            o_o4[i] = v;
        } else if (e < ns4 + no4 + 3L * N) {
            long s4 = e - ns4 - no4;
            int n = (int)(s4 / 3);
            int r = (int)(s4 - 3L * n);
            float4 v;
            const float* dc = feat_dc + 3 * n;
            const float* fr = feat_rest + 9 * n;
            if (r == 0) {
                v.x = __ldg(&dc[0]); v.y = __ldg(&dc[1]); v.z = __ldg(&dc[2]); v.w = __ldg(&fr[0]);
            } else if (r == 1) {
                v.x = __ldg(&fr[1]); v.y = __ldg(&fr[2]); v.z = __ldg(&fr[3]); v.w = __ldg(&fr[4]);
            } else {
                v.x = __ldg(&fr[5]); v.y = __ldg(&fr[6]); v.z = __ldg(&fr[7]); v.w = __ldg(&fr[8]);
            }
            o_sph4[s4] = v;
        }
        return;
    }

    // ================= main skinning path =================
    const int lane = threadIdx.x & 31;
    const int kl   = lane & 7;
    const int grp  = (lane >> 3) & 3;
    const long warp_gid = (long)blockIdx.x * (blockDim.x >> 5) + (threadIdx.x >> 5);
    const int n = (int)(warp_gid * 4 + grp);
    if (n >= N) return;   // N % 32 == 0 -> warps never partial

    const int a  = __ldg(&attach[n]);
    const int rt = __ldg(&ref_time[n]);
    const long rtM = (long)rt * M_NODES;

    // lane kl OWNS records 2kl (jj.x) and 2kl+1 (jj.y)
    const int2 jj = __ldg(&topo2[a * (KNN / 2) + kl]);

    const int base = lane & 24;        // group base lane (absolute)
    const int hf   = kl & 1;           // 0: load a-half, 1: load b-half
    const int comp = (kl >> 1) & 1;    // j component of my load-record
    const int quad = kl >> 2;          // owner offset within instruction

    // ---- pair-cooperative AB gather: load instr m covers records 4m..4m+3;
    // lane kl loads half hf of record r = 4m + (kl>>1); owner lane of r = 2m + quad.
    // Pairs share the record's 128B line -> 16 distinct lines/instr instead of 32.
    const float4* AB4 = (const float4*)g_AB;   // record j at float4 indices 2j, 2j+1
    int jm0, jm1, jm2, jm3;
    {
        int jx0 = __shfl_sync(0xffffffffu, jj.x, base + quad);
        int jy0 = __shfl_sync(0xffffffffu, jj.y, base + quad);
        int jx1 = __shfl_sync(0xffffffffu, jj.x, base + 2 + quad);
        int jy1 = __shfl_sync(0xffffffffu, jj.y, base + 2 + quad);
        int jx2 = __shfl_sync(0xffffffffu, jj.x, base + 4 + quad);
        int jy2 = __shfl_sync(0xffffffffu, jj.y, base + 4 + quad);
        int jx3 = __shfl_sync(0xffffffffu, jj.x, base + 6 + quad);
        int jy3 = __shfl_sync(0xffffffffu, jj.y, base + 6 + quad);
        jm0 = comp ? jy0 : jx0;
        jm1 = comp ? jy1 : jx1;
        jm2 = comp ? jy2 : jx2;
        jm3 = comp ? jy3 : jx3;
    }
    float4 v0 = __ldg(&AB4[(rtM + jm0) * 2 + hf]);
    float4 v1 = __ldg(&AB4[(rtM + jm1) * 2 + hf]);
    float4 v2 = __ldg(&AB4[(rtM + jm2) * 2 + hf]);
    float4 v3 = __ldg(&AB4[(rtM + jm3) * 2 + hf]);
    float4 C0v = __ldg(&g_C[jm0]);   // L1-hot; pair shares the line
    float4 C1v = __ldg(&g_C[jm1]);
    float4 C2v = __ldg(&g_C[jm2]);
    float4 C3v = __ldg(&g_C[jm3]);

    // ---- preamble (overlaps the gathers above) ----
    float4 Aa = __ldg(&AB4[(rtM + a) * 2]);
    Quat qa = qnormalize(qload(__ldg(&node_quat[rtM + a])));
    Quat qg = qnormalize(qload(__ldg(&gs_rot[n])));

    float3 gx = { __ldg(&gs_xyz[3 * n]), __ldg(&gs_xyz[3 * n + 1]), __ldg(&gs_xyz[3 * n + 2]) };
    float3 xr = qrot(qa, gx);
    float3 xw = { xr.x + Aa.x, xr.y + Aa.y, xr.z + Aa.z };
    Quat qag = qmul(qa, qg);   // unit*unit -> unit; R_world = R(qag)

    // ---- per-instruction pair compute. Even lane: w from a-half; odd lane: qrot
    // from b-half with (d, w) shuffled across the pair. Wrong-role garbage is
    // excluded via SEL (ternary), never multiplied (0*inf would NaN-poison).
    float accS = 0.f;
    float3 accMu = { 0.f, 0.f, 0.f };
    Quat accQb = { 0.f, 0.f, 0.f, 0.f };
    float wsav[4];   // valid on even lanes: w of record 4m + kl/2

    #pragma unroll
    for (int m = 0; m < 4; m++) {
        float4 vm = (m == 0) ? v0 : (m == 1) ? v1 : (m == 2) ? v2 : v3;
        float4 Cv = (m == 0) ? C0v : (m == 1) ? C1v : (m == 2) ? C2v : C3v;
        // even-lane role
        float3 d = { xw.x - vm.x, xw.y - vm.y, xw.z - vm.z };
        float dsq = d.x * d.x + d.y * d.y + d.z * d.z;
        float w = __expf(-dsq * vm.w);
        wsav[m] = w;
        // pair transfer (even -> odd)
        float dxr = __shfl_xor_sync(0xffffffffu, d.x, 1);
        float dyr = __shfl_xor_sync(0xffffffffu, d.y, 1);
        float dzr = __shfl_xor_sync(0xffffffffu, d.z, 1);
        float wr  = __shfl_xor_sync(0xffffffffu, w,   1);
        // odd-lane role
        Quat q; q.w = vm.x; q.x = vm.y; q.y = vm.z; q.z = vm.w;
        float3 dd = { dxr, dyr, dzr };
        float3 mv = qrot(q, dd);
        float wro = hf ? wr : 0.f;        // SEL: discards even-lane garbage wr
        float ws  = hf ? 0.f : w;         // SEL: discards odd-lane garbage w
        accS    += ws;
        accMu.x += wro * (mv.x + Cv.x);
        accMu.y += wro * (mv.y + Cv.y);
        accMu.z += wro * (mv.z + Cv.z);
        accQb.w += wro * q.w;
        accQb.x += wro * q.x;
        accQb.y += wro * q.y;
        accQb.z += wro * q.z;
    }

    // ---- group reductions (partials per role; totals complete across 8 lanes) ----
    float S   = qw_sum(accS);
    float mux = qw_sum(accMu.x);
    float muy = qw_sum(accMu.y);
    float muz = qw_sum(accMu.z);
    float qbw = qw_sum(accQb.w);
    float qbx = qw_sum(accQb.x);
    float qby = qw_sum(accQb.y);
    float qbz = qw_sum(accQb.z);

    float invS = 1.f / (S + EPSV);

    // ---- sem blend: record k -> w at (register k>>2, even lane 2*(k&3));
    //                 j at (owner lane k>>1, component k&1) ----
    float4 sacc = make_float4(0.f, 0.f, 0.f, 0.f);
    #pragma unroll
    for (int k = 0; k < KNN; k++) {
        float wk = __shfl_sync(0xffffffffu, wsav[k >> 2], base + 2 * (k & 3));
        int   jk = (k & 1) ? __shfl_sync(0xffffffffu, jj.y, base + (k >> 1))
                           : __shfl_sync(0xffffffffu, jj.x, base + (k >> 1));
        float4 vv = __ldg(&node_sem4[(long)jk * (FSEM / 4) + kl]);
        sacc.x += wk * vv.x; sacc.y += wk * vv.y;
        sacc.z += wk * vv.z; sacc.w += wk * vv.w;
    }

    // ---- frame epilogue: EXPLICIT Rb @ Rw (clip-safe; see R8 failure).
    // invS scaling BEFORE normalize is load-bearing (R2 failure).
    Quat qbn; qbn.w = qbw * invS; qbn.x = qbx * invS; qbn.y = qby * invS; qbn.z = qbz * invS;
    qbn = qnormalize(qbn);
    float Rb[3][3]; q2R(qbn, Rb);
    float Rw[3][3]; q2R(qag, Rw);
    float Fr[3][3]; mat3mul(Rb, Rw, Fr);

    // ---- outputs ----
    float*  o_mu  = out;
    float*  o_fr  = out + 3L  * N;
    float4* o_sem = (float4*)(out + 28L * N);

    float muv = (kl == 0) ? mux : ((kl == 1) ? muy : muz);
    if (kl < 3) o_mu[3 * n + kl] = muv * invS;

    float frv = Fr[0][0];
    frv = (kl == 1) ? Fr[0][1] : frv;
    frv = (kl == 2) ? Fr[0][2] : frv;
    frv = (kl == 3) ? Fr[1][0] : frv;
    frv = (kl == 4) ? Fr[1][1] : frv;
    frv = (kl == 5) ? Fr[1][2] : frv;
    frv = (kl == 6) ? Fr[2][0] : frv;
    frv = (kl == 7) ? Fr[2][1] : frv;
    o_fr[9 * n + kl] = frv;
    if (kl == 0) o_fr[9 * n + 8] = Fr[2][2];

    float4 sv; sv.x = sacc.x * invS; sv.y = sacc.y * invS;
    sv.z = sacc.z * invS; sv.w = sacc.w * invS;
    o_sem[(long)n * (FSEM / 4) + kl] = sv;
}

extern "C" void kernel_launch(void* const* d_in, const int* in_sizes, int n_in,
                              void* d_out, int out_size) {
    const float*  gs_xyz     = (const float*)d_in[0];
    const float4* gs_rot     = (const float4*)d_in[1];
    const float4* gs_scal4   = (const float4*)d_in[2];
    const float4* gs_op4     = (const float4*)d_in[3];
    const float*  feat_dc    = (const float*)d_in[4];
    const float*  feat_rest  = (const float*)d_in[5];
    const float*  node_xyz   = (const float*)d_in[6];
    const float4* node_quat  = (const float4*)d_in[7];
    const float*  node_sigma = (const float*)d_in[8];
    const float4* node_sem4  = (const float4*)d_in[9];
    const int*    attach     = (const int*)d_in[10];
    const int*    ref_time   = (const int*)d_in[11];
    const int2*   topo2      = (const int2*)d_in[12];
    const int*    t_ptr      = (const int*)d_in[13];

    int N = in_sizes[0] / 3;

    // 1) table precompute
    int pblocks = (T_STEPS * M_NODES + 255) / 256;
    dyn_scf_pre_kernel<<<pblocks, 256>>>(node_xyz, node_quat, node_sigma, t_ptr);

    // 2) fused main + elem
    int main_blocks = (N + 31) / 32;                       // 4 gaussians/warp, 8 warps/block
    long total4 = (3L * N) / 4 + (long)N / 4 + 3L * N;     // elem float4 units
    int elem_blocks = (int)((total4 + 255) / 256);
    dyn_scf_fused_kernel<<<main_blocks + elem_blocks, 256>>>(
        gs_xyz, gs_rot, node_quat, node_sem4,
        attach, ref_time, topo2,
        gs_scal4, gs_op4, feat_dc, feat_rest,
        (float*)d_out, N, main_blocks);
}